// round 2
// baseline (speedup 1.0000x reference)
#include <cuda_runtime.h>
#include <cuda_bf16.h>
#include <math.h>

// Problem constants
#define SEQ   2048
#define INDIM 256
#define H     512
#define R4H   2048   // 4*H
#define CTAS_PER_SIDE 64
#define TOTAL_CTAS    128

// ---------------- device scratch (static: no allocation allowed) ----------------
__device__ float    g_x[2][SEQ][INDIM];    // gathered embeddings, 4 MB
__device__ float    g_xp[2][SEQ][R4H];     // input projections + bias, 32 MB
__device__ float    g_h[2][2][H];          // double-buffered hidden state per side
__device__ unsigned g_cnt[2];              // per-side barrier counters (monotonic per launch)
__device__ unsigned g_fin;                 // final barrier

// ---------------- sync helpers ----------------
__device__ __forceinline__ unsigned ld_acq(const unsigned* p) {
    unsigned v;
    asm volatile("ld.acquire.gpu.u32 %0, [%1];" : "=r"(v) : "l"(p) : "memory");
    return v;
}

// ---------------- kernel 0: gather embeddings + reset state ----------------
// Token indices are int32: JAX materializes jnp.int64 as int32 (x64 disabled).
__global__ void __launch_bounds__(256) init_gather(const int* __restrict__ lidx,
                                                   const int* __restrict__ ridx,
                                                   const float* __restrict__ emb) {
    int bx = blockIdx.x;              // 0..4095
    int side = bx >> 11;              // 0..1
    int t = bx & (SEQ - 1);
    const int* idxp = side ? ridx : lidx;
    long long tok = (long long)idxp[t];
    g_x[side][t][threadIdx.x] = emb[tok * (long long)INDIM + threadIdx.x];

    if (bx == 0) {
        if (threadIdx.x < 2) g_cnt[threadIdx.x] = 0u;
        if (threadIdx.x == 2) g_fin = 0u;
        float* hp = &g_h[0][0][0];
        #pragma unroll
        for (int i = threadIdx.x; i < 2 * 2 * H; i += 256) hp[i] = 0.0f;
    }
}

// ---------------- kernel 1: xp = x @ W_ih^T + (b_ih + b_hh) ----------------
// C[2048 t][2048 r] = sum_k A[t][k] * B[r][k] + bias[r]; A,B both K-major.
// 128x128 tile, BK=16, 256 threads, 8x8 microtile.
__global__ void __launch_bounds__(256) gemm_xp(const float* __restrict__ W_ih,
                                               const float* __restrict__ b_ih,
                                               const float* __restrict__ b_hh) {
    int s  = blockIdx.z;
    int bm = blockIdx.y * 128;   // t offset
    int bn = blockIdx.x * 128;   // r offset
    const float* A = &g_x[s][0][0];   // [2048][256]
    const float* B = W_ih;            // [2048][256]

    __shared__ float As[16][128];
    __shared__ float Bs[16][128];

    int tid = threadIdx.x;
    int tx = tid & 15;       // 0..15 -> n
    int ty = tid >> 4;       // 0..15 -> m

    float acc[8][8];
    #pragma unroll
    for (int i = 0; i < 8; i++)
        #pragma unroll
        for (int jj = 0; jj < 8; jj++) acc[i][jj] = 0.0f;

    for (int k0 = 0; k0 < INDIM; k0 += 16) {
        #pragma unroll
        for (int i = 0; i < 2; i++) {
            int fidx = tid * 2 + i;          // 0..511
            int row = fidx >> 2;             // 0..127
            int kq  = fidx & 3;              // 0..3
            float4 v = *(const float4*)(A + (size_t)(bm + row) * INDIM + k0 + kq * 4);
            As[kq * 4 + 0][row] = v.x;
            As[kq * 4 + 1][row] = v.y;
            As[kq * 4 + 2][row] = v.z;
            As[kq * 4 + 3][row] = v.w;
            float4 u = *(const float4*)(B + (size_t)(bn + row) * INDIM + k0 + kq * 4);
            Bs[kq * 4 + 0][row] = u.x;
            Bs[kq * 4 + 1][row] = u.y;
            Bs[kq * 4 + 2][row] = u.z;
            Bs[kq * 4 + 3][row] = u.w;
        }
        __syncthreads();

        #pragma unroll
        for (int k = 0; k < 16; k++) {
            float a[8], b[8];
            *(float4*)(a)     = *(const float4*)&As[k][ty * 8];
            *(float4*)(a + 4) = *(const float4*)&As[k][ty * 8 + 4];
            *(float4*)(b)     = *(const float4*)&Bs[k][tx * 8];
            *(float4*)(b + 4) = *(const float4*)&Bs[k][tx * 8 + 4];
            #pragma unroll
            for (int mi = 0; mi < 8; mi++)
                #pragma unroll
                for (int ni = 0; ni < 8; ni++)
                    acc[mi][ni] += a[mi] * b[ni];
        }
        __syncthreads();
    }

    float bias[8];
    #pragma unroll
    for (int ni = 0; ni < 8; ni++) {
        int n = bn + tx * 8 + ni;
        bias[ni] = b_ih[n] + b_hh[n];
    }
    #pragma unroll
    for (int mi = 0; mi < 8; mi++) {
        int m = bm + ty * 8 + mi;
        float* cp = &g_xp[s][m][bn + tx * 8];
        float4 v0, v1;
        v0.x = acc[mi][0] + bias[0]; v0.y = acc[mi][1] + bias[1];
        v0.z = acc[mi][2] + bias[2]; v0.w = acc[mi][3] + bias[3];
        v1.x = acc[mi][4] + bias[4]; v1.y = acc[mi][5] + bias[5];
        v1.z = acc[mi][6] + bias[6]; v1.w = acc[mi][7] + bias[7];
        *(float4*)(cp)     = v0;
        *(float4*)(cp + 4) = v1;
    }
}

// ---------------- kernel 2: persistent LSTM scan ----------------
// 128 CTAs: CTAs [0,64) = side L, [64,128) = side R. 8 warps/CTA, 1 warp = 1 hidden unit.
// W_hh rows for unit j (gates i,f,g,o) live in registers: w[4][16] per lane.
__device__ __forceinline__ float sigmf(float x) { return 1.0f / (1.0f + expf(-x)); }

__global__ void __launch_bounds__(256) scan_kernel(const float* __restrict__ W_hh,
                                                   float* __restrict__ out) {
    const int side = blockIdx.x >> 6;          // /64
    const int cta  = blockIdx.x & 63;
    const int warp = threadIdx.x >> 5;
    const int lane = threadIdx.x & 31;
    const int j = cta * 8 + warp;              // hidden unit 0..511

    // Load recurrent weights into registers (one time)
    float w[4][16];
    #pragma unroll
    for (int g = 0; g < 4; g++) {
        const float* row = W_hh + (size_t)(g * H + j) * H + lane * 16;
        #pragma unroll
        for (int q = 0; q < 4; q++) {
            float4 v = *(const float4*)(row + q * 4);
            w[g][q * 4 + 0] = v.x; w[g][q * 4 + 1] = v.y;
            w[g][q * 4 + 2] = v.z; w[g][q * 4 + 3] = v.w;
        }
    }

    __shared__ float sh[H];
    const float* xps = &g_xp[side][0][0];
    unsigned* cnt = &g_cnt[side];
    float c = 0.0f;

    for (int t = 0; t < SEQ; t++) {
        const int rb = t & 1;          // read buffer
        const int wb = rb ^ 1;         // write buffer

        // xp for this unit at step t (uniform within warp)
        float xg0 = xps[(size_t)t * R4H + 0 * H + j];
        float xg1 = xps[(size_t)t * R4H + 1 * H + j];
        float xg2 = xps[(size_t)t * R4H + 2 * H + j];
        float xg3 = xps[(size_t)t * R4H + 3 * H + j];

        // Stage h into SMEM
        sh[threadIdx.x]       = g_h[side][rb][threadIdx.x];
        sh[threadIdx.x + 256] = g_h[side][rb][threadIdx.x + 256];
        __syncthreads();

        // Each lane: 16 consecutive h values
        float hr[16];
        const float4* sh4 = (const float4*)sh;
        #pragma unroll
        for (int q = 0; q < 4; q++) {
            float4 v = sh4[lane * 4 + q];
            hr[q * 4 + 0] = v.x; hr[q * 4 + 1] = v.y;
            hr[q * 4 + 2] = v.z; hr[q * 4 + 3] = v.w;
        }

        float acc0 = 0.0f, acc1 = 0.0f, acc2 = 0.0f, acc3 = 0.0f;
        #pragma unroll
        for (int i = 0; i < 16; i++) {
            acc0 += w[0][i] * hr[i];
            acc1 += w[1][i] * hr[i];
            acc2 += w[2][i] * hr[i];
            acc3 += w[3][i] * hr[i];
        }
        // warp-wide sum (butterfly leaves total in every lane)
        #pragma unroll
        for (int off = 16; off > 0; off >>= 1) {
            acc0 += __shfl_xor_sync(0xFFFFFFFFu, acc0, off);
            acc1 += __shfl_xor_sync(0xFFFFFFFFu, acc1, off);
            acc2 += __shfl_xor_sync(0xFFFFFFFFu, acc2, off);
            acc3 += __shfl_xor_sync(0xFFFFFFFFu, acc3, off);
        }

        float gi = sigmf(acc0 + xg0);
        float gf = sigmf(acc1 + xg1);
        float gg = tanhf(acc2 + xg2);
        float go = sigmf(acc3 + xg3);
        c = gf * c + gi * gg;
        float hval = go * tanhf(c);
        if (lane == 0) g_h[side][wb][j] = hval;

        // per-side grid barrier
        __syncthreads();
        if (threadIdx.x == 0) {
            __threadfence();
            atomicAdd(cnt, 1u);
            unsigned tgt = (unsigned)CTAS_PER_SIDE * (unsigned)(t + 1);
            while (ld_acq(cnt) < tgt) { }
        }
        __syncthreads();
    }

    // final cross-side barrier + output
    if (threadIdx.x == 0) {
        __threadfence();
        atomicAdd(&g_fin, 1u);
    }
    if (blockIdx.x == 0) {
        if (threadIdx.x == 0) {
            while (ld_acq(&g_fin) < (unsigned)TOTAL_CTAS) { }
        }
        __syncthreads();
        // final h lives in buffer (SEQ & 1) = 0
        float sv = 0.0f;
        for (int i = threadIdx.x; i < H; i += 256)
            sv += fabsf(g_h[0][0][i] - g_h[1][0][i]);
        #pragma unroll
        for (int off = 16; off > 0; off >>= 1)
            sv += __shfl_xor_sync(0xFFFFFFFFu, sv, off);
        if (lane == 0) sh[warp] = sv;
        __syncthreads();
        if (threadIdx.x == 0) {
            float s = 0.0f;
            #pragma unroll
            for (int wdx = 0; wdx < 8; wdx++) s += sh[wdx];
            out[0] = expf(-s);
        }
    }
}

// ---------------- launch ----------------
extern "C" void kernel_launch(void* const* d_in, const int* in_sizes, int n_in,
                              void* d_out, int out_size) {
    const int* lidx = (const int*)d_in[0];
    const int* ridx = (const int*)d_in[1];
    const float* emb  = (const float*)d_in[2];
    const float* W_ih = (const float*)d_in[3];
    const float* W_hh = (const float*)d_in[4];
    const float* b_ih = (const float*)d_in[5];
    const float* b_hh = (const float*)d_in[6];
    float* out = (float*)d_out;

    init_gather<<<4096, 256>>>(lidx, ridx, emb);
    gemm_xp<<<dim3(16, 16, 2), 256>>>(W_ih, b_ih, b_hh);
    scan_kernel<<<TOTAL_CTAS, 256>>>(W_hh, out);
}